// round 3
// baseline (speedup 1.0000x reference)
#include <cuda_runtime.h>
#include <math.h>

// Problem constants (from reference setup_inputs)
#define B 8
#define C 64
#define SPATIAL (48*48*48)        // 110592 floats per (b,c) channel
#define SPATIAL4 (SPATIAL/4)      // 27648 float4 per channel
#define SEGS 4                    // segments per row
#define SEG4 (SPATIAL4/SEGS)      // 6912 float4 per segment
#define NBLK (B*C*SEGS)           // 2048 blocks
#define R 8
#define NEG_SLOPE 0.01f

// Scratch (no cudaMalloc allowed)
__device__ float g_partials[NBLK];
__device__ int   g_idx[B * R];
__device__ int   g_count = 0;     // self-resetting ticket

// ---------------------------------------------------------------------------
// Kernel 1: fused mean + MLP + top-k.
// 2048 blocks: block s of row computes a quarter-row partial sum.
// The last block to finish reduces partials, runs the tiny MLP and top-8,
// and resets the ticket counter (graph-replay safe).
// ---------------------------------------------------------------------------
__global__ __launch_bounds__(256) void mean_mlp_topk_kernel(
    const float* __restrict__ x,
    const float* __restrict__ w1, const float* __restrict__ b1,
    const float* __restrict__ w2, const float* __restrict__ b2,
    int* __restrict__ idx_out) {

    const int blk = blockIdx.x;           // row*SEGS + seg
    const int row = blk >> 2;
    const int seg = blk & 3;
    const float4* __restrict__ p =
        reinterpret_cast<const float4*>(x + (size_t)row * SPATIAL) + seg * SEG4;

    float ax = 0.f, ay = 0.f, az = 0.f, aw = 0.f;
#pragma unroll 3
    for (int i = threadIdx.x; i < SEG4; i += 256) {   // 27 iterations
        float4 v = p[i];
        ax += v.x; ay += v.y; az += v.z; aw += v.w;
    }
    float acc = (ax + ay) + (az + aw);

    // warp reduce
    for (int off = 16; off > 0; off >>= 1)
        acc += __shfl_down_sync(0xFFFFFFFFu, acc, off);

    __shared__ float warp_sums[8];
    const int lane = threadIdx.x & 31;
    const int wid  = threadIdx.x >> 5;
    if (lane == 0) warp_sums[wid] = acc;
    __syncthreads();

    __shared__ bool is_last;
    if (threadIdx.x == 0) {
        float s = warp_sums[0] + warp_sums[1] + warp_sums[2] + warp_sums[3]
                + warp_sums[4] + warp_sums[5] + warp_sums[6] + warp_sums[7];
        g_partials[blk] = s;
        __threadfence();
        int old = atomicAdd(&g_count, 1);
        is_last = (old == NBLK - 1);
    }
    __syncthreads();
    if (!is_last) return;

    // ---------------- last block: reduce partials + MLP + topk ------------
    __shared__ float sm[B * C];     // means
    __shared__ float y1[B * C];
    __shared__ float y2[B * C];

    const int t = threadIdx.x;      // 0..255, each handles rows 2t, 2t+1
#pragma unroll
    for (int k = 0; k < 2; k++) {
        const int r2 = 2 * t + k;   // 0..511
        float4 ps = reinterpret_cast<const float4*>(g_partials)[r2];
        sm[r2] = ((ps.x + ps.y) + (ps.z + ps.w)) * (1.0f / (float)SPATIAL);
    }
    __syncthreads();

    // layer 1: y1[b][i] = leaky( means[b][:] . w1[i][:] + b1[i] )
#pragma unroll
    for (int k = 0; k < 2; k++) {
        const int u = t + k * 256;  // 0..511
        const int b = u >> 6, i = u & 63;
        float a = b1[i];
        const float* __restrict__ w1row = w1 + i * C;
        const float* __restrict__ mrow  = sm + b * C;
#pragma unroll 16
        for (int j = 0; j < C; j++) a += mrow[j] * w1row[j];
        y1[u] = (a > 0.0f) ? a : NEG_SLOPE * a;
    }
    __syncthreads();

    // layer 2: y2[b][i] = sigmoid( y1[b][:] . w2[i][:] + b2[i] )
#pragma unroll
    for (int k = 0; k < 2; k++) {
        const int u = t + k * 256;
        const int b = u >> 6, i = u & 63;
        float a = b2[i];
        const float* __restrict__ w2row = w2 + i * C;
        const float* __restrict__ y1row = y1 + b * C;
#pragma unroll 16
        for (int j = 0; j < C; j++) a += y1row[j] * w2row[j];
        y2[u] = 1.0f / (1.0f + expf(-a));
    }
    __syncthreads();

    // top-8 per batch; strict '>' keeps earliest index on ties (jax top_k).
    if (t < B) {
        float v[C];
#pragma unroll
        for (int j = 0; j < C; j++) v[j] = y2[t * C + j];
#pragma unroll
        for (int r = 0; r < R; r++) {
            int   best_j = 0;
            float best_v = v[0];
#pragma unroll
            for (int j = 1; j < C; j++)
                if (v[j] > best_v) { best_v = v[j]; best_j = j; }
            idx_out[t * R + r] = best_j;
            v[best_j] = -1.0f;   // sigmoid outputs are in (0,1)
        }
    }

    // reset ticket for next graph replay
    if (t == 0) g_count = 0;
}

// ---------------------------------------------------------------------------
// Kernel 2: gather selected channels: out[b][r][:] = x[b][idx[b][r]][:]
// grid = (27, 64); each thread copies 4 float4 (strided).
// ---------------------------------------------------------------------------
__global__ __launch_bounds__(256) void gather_kernel(const float* __restrict__ x,
                                                     const int* __restrict__ idx,
                                                     float* __restrict__ out) {
    const int row = blockIdx.y;          // 0..63 : b*R + r
    const int b   = row >> 3;
    const int ch  = idx[row];

    const float4* __restrict__ src =
        reinterpret_cast<const float4*>(x + ((size_t)b * C + ch) * SPATIAL);
    float4* __restrict__ dst =
        reinterpret_cast<float4*>(out + (size_t)row * SPATIAL);

    const int base = blockIdx.x * (256 * 4) + threadIdx.x;
#pragma unroll
    for (int k = 0; k < 4; k++) {
        const int i = base + k * 256;
        dst[i] = src[i];   // 27648 = 27*256*4 exactly: no bounds check
    }
}

// ---------------------------------------------------------------------------
extern "C" void kernel_launch(void* const* d_in, const int* in_sizes, int n_in,
                              void* d_out, int out_size) {
    const float* x  = (const float*)d_in[0];
    const float* w1 = (const float*)d_in[1];
    const float* b1 = (const float*)d_in[2];
    const float* w2 = (const float*)d_in[3];
    const float* b2 = (const float*)d_in[4];
    float* out = (float*)d_out;

    int* idx;
    cudaGetSymbolAddress((void**)&idx, g_idx);

    mean_mlp_topk_kernel<<<NBLK, 256>>>(x, w1, b1, w2, b2, idx);
    dim3 grid(SPATIAL4 / (256 * 4), B * R);   // (27, 64)
    gather_kernel<<<grid, 256>>>(x, idx, out);
}